// round 13
// baseline (speedup 1.0000x reference)
#include <cuda_runtime.h>
#include <cuda_bf16.h>
#include <cuda_fp16.h>
#include <math.h>
#include <float.h>
#include <stdint.h>

// Problem constants
#define NB   2
#define CC   128
#define HH   64
#define WW   64
#define HS   128
#define WS   128
#define HP   62          // HH - 2
#define USZ  126         // HS - 2
#define M_R  4096        // HH*WW
#define N_S  16384       // HS*WS

// Scratch. T is stored TILED for streaming argmax reads:
//   T'[n][jb][srow][i][djl][vs],  jb=j>>2 (16), srow (128), i (64), djl=j&3 (4), vs (128)
// element (r=(i,j), s=(srow,vs)) -> off = (((jb*128+srow)*64+i)<<9) + (djl<<7) + vs
static __device__ __half   g_Th[(size_t)NB * M_R * N_S];         // 268 MB
static __device__ uint32_t g_Apk[(size_t)NB * (CC/2) * M_R];
static __device__ uint32_t g_Bpk[(size_t)NB * (CC/2) * N_S];
static __device__ unsigned long long g_pack[NB * HP * HP];       // packed (key|~idx) argmax

__device__ __forceinline__ void cp_async16(uint32_t smem_addr, const void* gptr) {
    asm volatile("cp.async.cg.shared.global [%0], [%1], 16;\n"
                 :: "r"(smem_addr), "l"(gptr));
}

// ---------------------------------------------------------------------------
// Kernel 0: zero output scalar(s) + packed argmax array
// ---------------------------------------------------------------------------
__global__ void zero_kernel(float* out, int n) {
    int t = blockIdx.x * blockDim.x + threadIdx.x;
    if (t < n) out[t] = 0.0f;
    for (int x = t; x < NB * HP * HP; x += gridDim.x * blockDim.x)
        g_pack[x] = 0ull;
}

// ---------------------------------------------------------------------------
// Kernel 0b: pack fp32 [n][c][m] -> bf162 k-pair layout [n][k2][m]
// ---------------------------------------------------------------------------
__global__ void pack_kernel(const float* __restrict__ src, uint32_t* __restrict__ dst,
                            int M, int total) {
    for (int x = blockIdx.x * blockDim.x + threadIdx.x; x < total;
         x += gridDim.x * blockDim.x) {
        int m   = x % M;
        int nk2 = x / M;
        int n   = nk2 >> 6;
        int k2  = nk2 & 63;
        const float* s = src + ((size_t)(n * CC + 2 * k2)) * M + m;
        __nv_bfloat162 h = __floats2bfloat162_rn(s[0], s[M]);
        dst[x] = *(uint32_t*)&h;
    }
}

// ---------------------------------------------------------------------------
// Kernel 1: GEMM bf16 HMMA (R8-proven), SPITCH=136, f16 smem-staged epilogue.
// Only the final store ADDRESS changed to the tiled T' layout.
// ---------------------------------------------------------------------------
#define BM 128
#define BN 128
#define BK2 16
#define SPITCH 136
#define CPITCH 136       // epilogue staging pitch in HALVES (272B rows, 16B mult)

__global__ __launch_bounds__(256) void gemm_kernel() {
    __shared__ __align__(16) uint32_t As2[2][BK2 * SPITCH];
    __shared__ __align__(16) uint32_t Bs2[2][BK2 * SPITCH];

    const int n = blockIdx.z;
    const uint32_t* Ap = g_Apk + (size_t)n * (CC / 2) * M_R;
    const uint32_t* Bp = g_Bpk + (size_t)n * (CC / 2) * N_S;
    __half*         Ct = g_Th  + (size_t)n * M_R * N_S;

    const int r0 = blockIdx.y * BM;
    const int s0 = blockIdx.x * BN;
    const int srow = blockIdx.x;          // s0 / 128
    const int tid  = threadIdx.x;
    const int lane = tid & 31;
    const int wid  = tid >> 5;
    const int wg   = wid >> 2;
    const int warp_m = wg * 64;
    const int warp_n = (wid & 3) * 32;
    const int g    = lane >> 2;
    const int tid4 = lane & 3;

    const uint32_t sA = (uint32_t)__cvta_generic_to_shared(&As2[0][0]);
    const uint32_t sB = (uint32_t)__cvta_generic_to_shared(&Bs2[0][0]);

    auto issue = [&](int buf, int kk2) {
#pragma unroll
        for (int h = 0; h < 2; h++) {
            int ch = tid + h * 256;
            int k2 = ch >> 5;
            int m4 = (ch & 31) << 2;
            uint32_t doff = (uint32_t)((buf * BK2 * SPITCH + k2 * SPITCH + m4) * 4);
            cp_async16(sA + doff, Ap + (size_t)(kk2 + k2) * M_R + r0 + m4);
            cp_async16(sB + doff, Bp + (size_t)(kk2 + k2) * N_S + s0 + m4);
        }
        asm volatile("cp.async.commit_group;\n" ::: "memory");
    };

    float acc[4][4][4];
#pragma unroll
    for (int mt = 0; mt < 4; mt++)
#pragma unroll
        for (int nt = 0; nt < 4; nt++)
#pragma unroll
            for (int q = 0; q < 4; q++) acc[mt][nt][q] = 0.0f;

    issue(0, 0);

    const int NSTAGE = (CC / 2) / BK2;
#pragma unroll
    for (int s = 0; s < NSTAGE; s++) {
        if (s + 1 < NSTAGE) {
            issue((s + 1) & 1, (s + 1) * BK2);
            asm volatile("cp.async.wait_group 1;\n" ::: "memory");
        } else {
            asm volatile("cp.async.wait_group 0;\n" ::: "memory");
        }
        __syncthreads();

        const uint32_t* Ab = &As2[s & 1][0];
        const uint32_t* Bb = &Bs2[s & 1][0];
#pragma unroll
        for (int kc2 = 0; kc2 < BK2; kc2 += 8) {
            uint32_t af[4][4], bfr[4][2];
#pragma unroll
            for (int mt = 0; mt < 4; mt++) {
                int m = warp_m + mt * 16 + g;
                af[mt][0] = Ab[(kc2 + tid4)     * SPITCH + m];
                af[mt][1] = Ab[(kc2 + tid4)     * SPITCH + m + 8];
                af[mt][2] = Ab[(kc2 + tid4 + 4) * SPITCH + m];
                af[mt][3] = Ab[(kc2 + tid4 + 4) * SPITCH + m + 8];
            }
#pragma unroll
            for (int nt = 0; nt < 4; nt++) {
                int nn = warp_n + nt * 8 + g;
                bfr[nt][0] = Bb[(kc2 + tid4)     * SPITCH + nn];
                bfr[nt][1] = Bb[(kc2 + tid4 + 4) * SPITCH + nn];
            }
#pragma unroll
            for (int mt = 0; mt < 4; mt++)
#pragma unroll
                for (int nt = 0; nt < 4; nt++) {
                    asm volatile(
                        "mma.sync.aligned.m16n8k16.row.col.f32.bf16.bf16.f32 "
                        "{%0,%1,%2,%3},{%4,%5,%6,%7},{%8,%9},{%0,%1,%2,%3};"
                        : "+f"(acc[mt][nt][0]), "+f"(acc[mt][nt][1]),
                          "+f"(acc[mt][nt][2]), "+f"(acc[mt][nt][3])
                        : "r"(af[mt][0]), "r"(af[mt][1]), "r"(af[mt][2]), "r"(af[mt][3]),
                          "r"(bfr[nt][0]), "r"(bfr[nt][1]));
                }
        }
        __syncthreads();
    }

    // ---- Epilogue: stage f16 through smem (R8 layout), store to tiled T' ----
    __half* Cs = (__half*)&As2[0][0];
#pragma unroll
    for (int mt = 0; mt < 4; mt++) {
        __syncthreads();
        const int rl0 = wg * 16 + g;
#pragma unroll
        for (int nt = 0; nt < 4; nt++) {
            int col = warp_n + nt * 8 + 2 * tid4;
            *(__half2*)&Cs[rl0 * CPITCH + col] =
                __floats2half2_rn(acc[mt][nt][0], acc[mt][nt][1]);
            *(__half2*)&Cs[(rl0 + 8) * CPITCH + col] =
                __floats2half2_rn(acc[mt][nt][2], acc[mt][nt][3]);
        }
        __syncthreads();
#pragma unroll
        for (int h = 0; h < 2; h++) {
            int c = tid + h * 256;        // 0..511
            int rl = c >> 4;              // 0..31
            int seg = c & 15;
            uint4 v = *(uint4*)&Cs[rl * CPITCH + seg * 8];
            int grow = r0 + mt * 16 + ((rl >> 4) ? 64 : 0) + (rl & 15);
            int gi = grow >> 6;           // ref i
            int gj = grow & 63;           // ref j
            size_t off = ((size_t)(((gj >> 2) * 128 + srow) * 64 + gi) << 9)
                       + ((size_t)(gj & 3) << 7) + seg * 8;
            *(uint4*)(Ct + off) = v;      // 16B aligned
        }
    }
}

// ---------------------------------------------------------------------------
// Kernel 2: argmax v4 (R7-proven compute) with TILED T' reads:
// per srow-step one 6KB contiguous chunk (own j-group) + 6 x 512B (neighbor).
// Block = 256 thr = 16 px (4x4) x 16 subs; us-split x2; ring-5 smem (45KB).
// ---------------------------------------------------------------------------
__global__ __launch_bounds__(256) void argmax_kernel() {
    __shared__ __align__(16) __half buf[5][36][128];   // 45 KB

    const int n    = blockIdx.z & 1;
    const int part = blockIdx.z >> 1;
    const int base = part * 63;           // us range [base, base+63)
    const int tid = threadIdx.x;
    const int px  = tid >> 4;
    const int sub = tid & 15;
    const int di  = px >> 2;
    const int dj  = px & 3;
    const int i0  = blockIdx.y * 4;
    const int j0  = blockIdx.x * 4;
    const int i   = i0 + di;
    const int j   = j0 + dj;
    const int vs0 = sub << 3;
    const int jb0 = blockIdx.x;           // j0 >> 2

    const __half* Tn = g_Th + (size_t)n * M_R * N_S;

    // load shape row (base+lr) into ring slot: 576 16B chunks
    auto issue_srow = [&](int lr, int slot) {
        int srow = base + lr;
#pragma unroll
        for (int it2 = 0; it2 < 3; it2++) {
            int c = tid + it2 * 256;
            if (c < 576) {
                int r36 = c >> 4;             // i'*6 + dj'
                int seg = c & 15;
                int ip  = r36 / 6;
                int djp = r36 - ip * 6;
                int ri  = min(i0 + ip, HH - 1);
                int jb, djl;
                if (djp < 4) { jb = jb0; djl = djp; }
                else if (jb0 < 15) { jb = jb0 + 1; djl = djp - 4; }
                else { jb = 15; djl = djp - 2; }   // garbage, masked pixels only
                const __half* src = Tn
                    + ((size_t)((jb * 128 + srow) * 64 + ri) << 9)
                    + ((size_t)djl << 7) + seg * 8;
                uint32_t daddr = (uint32_t)__cvta_generic_to_shared(
                    &buf[slot][r36][seg * 8]);
                cp_async16(daddr, src);
            }
        }
        asm volatile("cp.async.commit_group;\n" ::: "memory");
    };

    issue_srow(0, 0); issue_srow(1, 1); issue_srow(2, 2); issue_srow(3, 3);

    const __half NEG_INF = __ushort_as_half((unsigned short)0xFC00);
    const __half2 NEG2   = __halves2half2(NEG_INF, NEG_INF);
    __half best_h = NEG_INF;
    int    bidx   = 0;
    const bool tail  = (sub == 15);
    const bool valid = (i < HP) && (j < HP);

    int s0 = 0;   // ring slot of row k
    for (int k = 0; k < 63; k++) {
        if (k == 62) {
            asm volatile("cp.async.wait_group 0;\n" ::: "memory");
        } else {
            asm volatile("cp.async.wait_group 1;\n" ::: "memory");
        }
        __syncthreads();

        if (k <= 60) {
            int sw = (s0 == 0) ? 4 : s0 - 1;
            issue_srow(k + 4, sw);
        }

        int s1 = s0 + 1; if (s1 == 5) s1 = 0;
        int s2 = s1 + 1; if (s2 == 5) s2 = 0;
        const __half* sp[3] = { &buf[s0][0][0], &buf[s1][0][0], &buf[s2][0][0] };

        __half2 S[4];
#pragma unroll
        for (int q = 0; q < 4; q++) S[q] = __float2half2_rn(0.0f);

#pragma unroll
        for (int a = 0; a < 3; a++) {
            const __half* slotp = sp[a];
#pragma unroll
            for (int b = 0; b < 3; b++) {
                const __half* p = slotp + ((di + a) * 6 + (dj + b)) * 128 + vs0;
                uint4 v = *(const uint4*)p;
                uint32_t u4 = __shfl_down_sync(0xffffffffu, v.x, 1);
                __half2 h0 = *(__half2*)&v.x;
                __half2 h1 = *(__half2*)&v.y;
                __half2 h2 = *(__half2*)&v.z;
                __half2 h3 = *(__half2*)&v.w;
                __half2 h4 = *(__half2*)&u4;
                if (b == 0) {
                    S[0] = __hadd2(S[0], h0);
                    S[1] = __hadd2(S[1], h1);
                    S[2] = __hadd2(S[2], h2);
                    S[3] = __hadd2(S[3], h3);
                } else if (b == 1) {
                    uint32_t u0 = *(uint32_t*)&h0, u1 = *(uint32_t*)&h1;
                    uint32_t u2 = *(uint32_t*)&h2, u3 = *(uint32_t*)&h3;
                    uint32_t u4b = *(uint32_t*)&h4;
                    uint32_t w0 = __byte_perm(u0, u1, 0x5432);
                    uint32_t w1 = __byte_perm(u1, u2, 0x5432);
                    uint32_t w2 = __byte_perm(u2, u3, 0x5432);
                    uint32_t w3 = __byte_perm(u3, u4b, 0x5432);
                    S[0] = __hadd2(S[0], *(__half2*)&w0);
                    S[1] = __hadd2(S[1], *(__half2*)&w1);
                    S[2] = __hadd2(S[2], *(__half2*)&w2);
                    S[3] = __hadd2(S[3], *(__half2*)&w3);
                } else {
                    S[0] = __hadd2(S[0], h1);
                    S[1] = __hadd2(S[1], h2);
                    S[2] = __hadd2(S[2], h3);
                    S[3] = __hadd2(S[3], h4);
                }
            }
        }
        if (tail) S[3] = NEG2;

        __half2 m01 = __hmax2(S[0], S[1]);
        __half2 m23 = __hmax2(S[2], S[3]);
        __half2 m   = __hmax2(m01, m23);
        __half  mh  = __hmax(__low2half(m), __high2half(m));

        if (__hgt(mh, best_h)) {
            best_h = mh;
            const int ubase = (base + k) * USZ + vs0;
            bool found = false;
#pragma unroll
            for (int q = 0; q < 4; q++) {
                if (!found && __heq(__low2half(S[q]), mh))  { bidx = ubase + 2 * q;     found = true; }
                if (!found && __heq(__high2half(S[q]), mh)) { bidx = ubase + 2 * q + 1; found = true; }
            }
        }

        s0 = s1;
    }

    // per-pixel reduce over the 16 subs (16 consecutive lanes)
    float best = valid ? __half2float(best_h) : -FLT_MAX;
#pragma unroll
    for (int off = 8; off > 0; off >>= 1) {
        float ov = __shfl_xor_sync(0xffffffffu, best, off);
        int   oi = __shfl_xor_sync(0xffffffffu, bidx, off);
        if (ov > best || (ov == best && oi < bidx)) { best = ov; bidx = oi; }
    }
    if (valid && sub == 0) {
        uint32_t fb  = __float_as_uint(best);
        uint32_t key = ((int)fb < 0) ? ~fb : (fb | 0x80000000u);
        unsigned long long pk =
            ((unsigned long long)key << 32) | (uint32_t)(0xFFFFFFFFu - (uint32_t)bidx);
        atomicMax(&g_pack[(n * HP + i) * HP + j], pk);
    }
}

// ---------------------------------------------------------------------------
// Kernel 3: gather matched color patch, L1, clip, global sum (unchanged).
// ---------------------------------------------------------------------------
__global__ __launch_bounds__(1024) void l1_kernel(const float* __restrict__ outf,
                                                  const float* __restrict__ colf,
                                                  float* __restrict__ dout) {
    const int i = blockIdx.x;
    const int n = blockIdx.y;

    __shared__ float l1s[HP];
    __shared__ int   uu[HP];
    if (threadIdx.x < HP) {
        l1s[threadIdx.x] = 0.0f;
        unsigned long long pk = g_pack[(n * HP + i) * HP + threadIdx.x];
        uu[threadIdx.x] = (int)(0xFFFFFFFFu - (uint32_t)(pk & 0xFFFFFFFFull));
    }
    __syncthreads();

    for (int t = threadIdx.x; t < CC * HP; t += 1024) {
        int c = t / HP;
        int j = t - c * HP;
        int u  = uu[j];
        int us = u / USZ;
        int vs = u - us * USZ;

        const float* op = outf + ((size_t)(n * CC + c) * HH + i)  * WW + j;
        const float* cp = colf + ((size_t)(n * CC + c) * HS + us) * WS + vs;

        float s = 0.0f;
#pragma unroll
        for (int a = 0; a < 3; a++)
#pragma unroll
            for (int b = 0; b < 3; b++)
                s += fabsf(op[a * WW + b] - cp[a * WS + b]);
        atomicAdd(&l1s[j], s);
    }
    __syncthreads();

    if (threadIdx.x < HP) {
        float v = fminf(fmaxf(l1s[threadIdx.x], 0.0f), 1000.0f);
        atomicAdd(dout, v);
    }
}

// ---------------------------------------------------------------------------
// Launch
// ---------------------------------------------------------------------------
extern "C" void kernel_launch(void* const* d_in, const int* in_sizes, int n_in,
                              void* d_out, int out_size) {
    const float* output_feat = (const float*)d_in[0];
    const float* ref_feat    = (const float*)d_in[1];
    const float* shape_feat  = (const float*)d_in[2];
    const float* color_feat  = (const float*)d_in[3];
    float* out = (float*)d_out;

    zero_kernel<<<32, 256>>>(out, out_size);

    pack_kernel<<<256, 256>>>(ref_feat,   g_Apk, M_R, NB * (CC / 2) * M_R);
    pack_kernel<<<512, 256>>>(shape_feat, g_Bpk, N_S, NB * (CC / 2) * N_S);

    dim3 g1(N_S / BN, M_R / BM, NB);
    gemm_kernel<<<g1, 256>>>();

    dim3 g2(16, 16, NB * 2);
    argmax_kernel<<<g2, 256>>>();

    dim3 g3(HP, NB);
    l1_kernel<<<g3, 1024>>>(output_feat, color_feat, out);
}

// round 15
// speedup vs baseline: 1.1877x; 1.1877x over previous
#include <cuda_runtime.h>
#include <cuda_bf16.h>
#include <cuda_fp16.h>
#include <math.h>
#include <float.h>
#include <stdint.h>

// Problem constants
#define NB   2
#define CC   128
#define HH   64
#define WW   64
#define HS   128
#define WS   128
#define HP   62          // HH - 2
#define USZ  126         // HS - 2
#define M_R  4096        // HH*WW
#define N_S  16384       // HS*WS

// Scratch
static __device__ __half   g_Th[(size_t)NB * M_R * N_S];         // 268 MB f16 Gram matrix
static __device__ uint32_t g_Apk[(size_t)NB * (CC/2) * M_R];     // 2 MB  bf162 k-pair packed ref
static __device__ uint32_t g_Bpk[(size_t)NB * (CC/2) * N_S];     // 8 MB  bf162 k-pair packed shape
static __device__ unsigned long long g_pack[NB * HP * HP];       // packed (key|~idx) argmax

__device__ __forceinline__ void cp_async16(uint32_t smem_addr, const void* gptr) {
    asm volatile("cp.async.cg.shared.global [%0], [%1], 16;\n"
                 :: "r"(smem_addr), "l"(gptr));
}

// ---------------------------------------------------------------------------
// Kernel 0b: pack fp32 [n][c][m] -> bf162 k-pair layout [n][k2][m].
// Block 0 additionally zeroes the output scalar(s) and the packed argmax
// array (runs before argmax/l1 in stream order).
// ---------------------------------------------------------------------------
__global__ void pack_kernel(const float* __restrict__ src, uint32_t* __restrict__ dst,
                            int M, int total, float* out, int out_n) {
    if (blockIdx.x == 0) {
        for (int t = threadIdx.x; t < out_n; t += blockDim.x) out[t] = 0.0f;
        for (int t = threadIdx.x; t < NB * HP * HP; t += blockDim.x)
            g_pack[t] = 0ull;
    }
    for (int x = blockIdx.x * blockDim.x + threadIdx.x; x < total;
         x += gridDim.x * blockDim.x) {
        int m   = x % M;
        int nk2 = x / M;
        int n   = nk2 >> 6;
        int k2  = nk2 & 63;
        const float* s = src + ((size_t)(n * CC + 2 * k2)) * M + m;
        __nv_bfloat162 h = __floats2bfloat162_rn(s[0], s[M]);
        dst[x] = *(uint32_t*)&h;
    }
}

// ---------------------------------------------------------------------------
// Kernel 1: GEMM bf16 HMMA (R8-proven), SPITCH=136, f16 smem-staged epilogue.
// launch_bounds(256,2) pins regs <= 128 (2 blocks/SM). Epilogue alternates
// the As2/Bs2 areas as staging buffers -> 1 barrier per mt instead of 2.
// ---------------------------------------------------------------------------
#define BM 128
#define BN 128
#define BK2 16
#define SPITCH 136
#define CPITCH 136       // epilogue staging pitch in HALVES (272B rows)

__global__ __launch_bounds__(256, 2) void gemm_kernel() {
    __shared__ __align__(16) uint32_t As2[2][BK2 * SPITCH];
    __shared__ __align__(16) uint32_t Bs2[2][BK2 * SPITCH];

    const int n = blockIdx.z;
    const uint32_t* Ap = g_Apk + (size_t)n * (CC / 2) * M_R;
    const uint32_t* Bp = g_Bpk + (size_t)n * (CC / 2) * N_S;
    __half*         Ct = g_Th  + (size_t)n * M_R * N_S;

    const int r0 = blockIdx.y * BM;
    const int s0 = blockIdx.x * BN;
    const int tid  = threadIdx.x;
    const int lane = tid & 31;
    const int wid  = tid >> 5;
    const int wg   = wid >> 2;
    const int warp_m = wg * 64;
    const int warp_n = (wid & 3) * 32;
    const int g    = lane >> 2;
    const int tid4 = lane & 3;

    const uint32_t sA = (uint32_t)__cvta_generic_to_shared(&As2[0][0]);
    const uint32_t sB = (uint32_t)__cvta_generic_to_shared(&Bs2[0][0]);

    auto issue = [&](int buf, int kk2) {
#pragma unroll
        for (int h = 0; h < 2; h++) {
            int ch = tid + h * 256;
            int k2 = ch >> 5;
            int m4 = (ch & 31) << 2;
            uint32_t doff = (uint32_t)((buf * BK2 * SPITCH + k2 * SPITCH + m4) * 4);
            cp_async16(sA + doff, Ap + (size_t)(kk2 + k2) * M_R + r0 + m4);
            cp_async16(sB + doff, Bp + (size_t)(kk2 + k2) * N_S + s0 + m4);
        }
        asm volatile("cp.async.commit_group;\n" ::: "memory");
    };

    float acc[4][4][4];
#pragma unroll
    for (int mt = 0; mt < 4; mt++)
#pragma unroll
        for (int nt = 0; nt < 4; nt++)
#pragma unroll
            for (int q = 0; q < 4; q++) acc[mt][nt][q] = 0.0f;

    issue(0, 0);

    const int NSTAGE = (CC / 2) / BK2;
#pragma unroll
    for (int s = 0; s < NSTAGE; s++) {
        if (s + 1 < NSTAGE) {
            issue((s + 1) & 1, (s + 1) * BK2);
            asm volatile("cp.async.wait_group 1;\n" ::: "memory");
        } else {
            asm volatile("cp.async.wait_group 0;\n" ::: "memory");
        }
        __syncthreads();

        const uint32_t* Ab = &As2[s & 1][0];
        const uint32_t* Bb = &Bs2[s & 1][0];
#pragma unroll
        for (int kc2 = 0; kc2 < BK2; kc2 += 8) {
            uint32_t af[4][4], bfr[4][2];
#pragma unroll
            for (int mt = 0; mt < 4; mt++) {
                int m = warp_m + mt * 16 + g;
                af[mt][0] = Ab[(kc2 + tid4)     * SPITCH + m];
                af[mt][1] = Ab[(kc2 + tid4)     * SPITCH + m + 8];
                af[mt][2] = Ab[(kc2 + tid4 + 4) * SPITCH + m];
                af[mt][3] = Ab[(kc2 + tid4 + 4) * SPITCH + m + 8];
            }
#pragma unroll
            for (int nt = 0; nt < 4; nt++) {
                int nn = warp_n + nt * 8 + g;
                bfr[nt][0] = Bb[(kc2 + tid4)     * SPITCH + nn];
                bfr[nt][1] = Bb[(kc2 + tid4 + 4) * SPITCH + nn];
            }
#pragma unroll
            for (int mt = 0; mt < 4; mt++)
#pragma unroll
                for (int nt = 0; nt < 4; nt++) {
                    asm volatile(
                        "mma.sync.aligned.m16n8k16.row.col.f32.bf16.bf16.f32 "
                        "{%0,%1,%2,%3},{%4,%5,%6,%7},{%8,%9},{%0,%1,%2,%3};"
                        : "+f"(acc[mt][nt][0]), "+f"(acc[mt][nt][1]),
                          "+f"(acc[mt][nt][2]), "+f"(acc[mt][nt][3])
                        : "r"(af[mt][0]), "r"(af[mt][1]), "r"(af[mt][2]), "r"(af[mt][3]),
                          "r"(bfr[nt][0]), "r"(bfr[nt][1]));
                }
        }
        __syncthreads();
    }

    // ---- Epilogue: alternate staging buffers (As2-area / Bs2-area),
    //      one barrier per 32-row chunk. ----
    __half* CsA = (__half*)&As2[0][0];
    __half* CsB = (__half*)&Bs2[0][0];
#pragma unroll
    for (int mt = 0; mt < 4; mt++) {
        __half* Cs = (mt & 1) ? CsB : CsA;
        const int rl0 = wg * 16 + g;
#pragma unroll
        for (int nt = 0; nt < 4; nt++) {
            int col = warp_n + nt * 8 + 2 * tid4;
            *(__half2*)&Cs[rl0 * CPITCH + col] =
                __floats2half2_rn(acc[mt][nt][0], acc[mt][nt][1]);
            *(__half2*)&Cs[(rl0 + 8) * CPITCH + col] =
                __floats2half2_rn(acc[mt][nt][2], acc[mt][nt][3]);
        }
        __syncthreads();
#pragma unroll
        for (int h = 0; h < 2; h++) {
            int c = tid + h * 256;        // 0..511
            int rl = c >> 4;              // 0..31
            int seg = c & 15;
            uint4 v = *(uint4*)&Cs[rl * CPITCH + seg * 8];
            int grow = r0 + mt * 16 + ((rl >> 4) ? 64 : 0) + (rl & 15);
            *(uint4*)(Ct + (size_t)grow * N_S + s0 + seg * 8) = v;
        }
    }
}

// ---------------------------------------------------------------------------
// Kernel 2: argmax v4 (R8-proven) with two latency fixes:
//  - prefetch issued immediately after the entry barrier (WAR-safe)
//  - wait_group relaxed to 2 (exactly rows <= k+2 guaranteed), tail 1/0.
// Block = 256 thr = 16 px (4x4) x 16 subs (8 vs each); us-split x2; ring-5.
// ---------------------------------------------------------------------------
__global__ __launch_bounds__(256) void argmax_kernel() {
    __shared__ __align__(16) __half buf[5][36][128];   // 45 KB

    const int n    = blockIdx.z & 1;
    const int part = blockIdx.z >> 1;
    const int base = part * 63;           // us range [base, base+63)
    const int tid = threadIdx.x;
    const int px  = tid >> 4;
    const int sub = tid & 15;
    const int di  = px >> 2;
    const int dj  = px & 3;
    const int i0  = blockIdx.y * 4;
    const int j0  = blockIdx.x * 4;
    const int i   = i0 + di;
    const int j   = j0 + dj;
    const int vs0 = sub << 3;

    const __half* Tn = g_Th + (size_t)n * M_R * N_S;

    auto issue_srow = [&](int lr, int slot) {
        int srow = base + lr;
#pragma unroll
        for (int it = 0; it < 3; it++) {
            int c = tid + it * 256;
            if (c < 576) {
                int r36 = c >> 4;
                int seg = c & 15;
                int t = r36 / 6, w = r36 - t * 6;
                int ri = min(i0 + t, HH - 1);
                int rj = min(j0 + w, WW - 1);
                const __half* src = Tn + (size_t)(ri * WW + rj) * N_S + srow * 128 + seg * 8;
                uint32_t daddr = (uint32_t)__cvta_generic_to_shared(&buf[slot][r36][seg * 8]);
                cp_async16(daddr, src);
            }
        }
        asm volatile("cp.async.commit_group;\n" ::: "memory");
    };

    issue_srow(0, 0); issue_srow(1, 1); issue_srow(2, 2); issue_srow(3, 3);

    const __half NEG_INF = __ushort_as_half((unsigned short)0xFC00);
    const __half2 NEG2   = __halves2half2(NEG_INF, NEG_INF);
    __half best_h = NEG_INF;
    int    bidx   = 0;
    const bool tail  = (sub == 15);
    const bool valid = (i < HP) && (j < HP);

    int s0 = 0;
    for (int k = 0; k < 63; k++) {
        // need rows k..k+2 complete. Groups issued so far cover rows <= k+3
        // (prologue 0..3, steps 0..k-1 added 4..k+3).
        if (k < 61) {
            asm volatile("cp.async.wait_group 2;\n" ::: "memory");   // rows <= k+1?  see note
        } else if (k == 61) {
            asm volatile("cp.async.wait_group 1;\n" ::: "memory");
        } else {
            asm volatile("cp.async.wait_group 0;\n" ::: "memory");
        }
        __syncthreads();

        // issue row k+4 into the slot that held row k-1 (last read at step
        // k-1, ordered by this step's barrier) BEFORE compute, for overlap.
        if (k <= 60) {
            int sw = (s0 == 0) ? 4 : s0 - 1;
            issue_srow(k + 4, sw);
        }

        int s1 = s0 + 1; if (s1 == 5) s1 = 0;
        int s2 = s1 + 1; if (s2 == 5) s2 = 0;
        const __half* sp[3] = { &buf[s0][0][0], &buf[s1][0][0], &buf[s2][0][0] };

        __half2 S[4];
#pragma unroll
        for (int q = 0; q < 4; q++) S[q] = __float2half2_rn(0.0f);

#pragma unroll
        for (int a = 0; a < 3; a++) {
            const __half* slotp = sp[a];
#pragma unroll
            for (int b = 0; b < 3; b++) {
                const __half* p = slotp + ((di + a) * 6 + (dj + b)) * 128 + vs0;
                uint4 v = *(const uint4*)p;
                uint32_t u4 = __shfl_down_sync(0xffffffffu, v.x, 1);
                __half2 h0 = *(__half2*)&v.x;
                __half2 h1 = *(__half2*)&v.y;
                __half2 h2 = *(__half2*)&v.z;
                __half2 h3 = *(__half2*)&v.w;
                __half2 h4 = *(__half2*)&u4;
                if (b == 0) {
                    S[0] = __hadd2(S[0], h0);
                    S[1] = __hadd2(S[1], h1);
                    S[2] = __hadd2(S[2], h2);
                    S[3] = __hadd2(S[3], h3);
                } else if (b == 1) {
                    uint32_t u0 = *(uint32_t*)&h0, u1 = *(uint32_t*)&h1;
                    uint32_t u2 = *(uint32_t*)&h2, u3 = *(uint32_t*)&h3;
                    uint32_t u4b = *(uint32_t*)&h4;
                    uint32_t w0 = __byte_perm(u0, u1, 0x5432);
                    uint32_t w1 = __byte_perm(u1, u2, 0x5432);
                    uint32_t w2 = __byte_perm(u2, u3, 0x5432);
                    uint32_t w3 = __byte_perm(u3, u4b, 0x5432);
                    S[0] = __hadd2(S[0], *(__half2*)&w0);
                    S[1] = __hadd2(S[1], *(__half2*)&w1);
                    S[2] = __hadd2(S[2], *(__half2*)&w2);
                    S[3] = __hadd2(S[3], *(__half2*)&w3);
                } else {
                    S[0] = __hadd2(S[0], h1);
                    S[1] = __hadd2(S[1], h2);
                    S[2] = __hadd2(S[2], h3);
                    S[3] = __hadd2(S[3], h4);
                }
            }
        }
        if (tail) S[3] = NEG2;

        __half2 m01 = __hmax2(S[0], S[1]);
        __half2 m23 = __hmax2(S[2], S[3]);
        __half2 m   = __hmax2(m01, m23);
        __half  mh  = __hmax(__low2half(m), __high2half(m));

        if (__hgt(mh, best_h)) {
            best_h = mh;
            const int ubase = (base + k) * USZ + vs0;
            bool found = false;
#pragma unroll
            for (int q = 0; q < 4; q++) {
                if (!found && __heq(__low2half(S[q]), mh))  { bidx = ubase + 2 * q;     found = true; }
                if (!found && __heq(__high2half(S[q]), mh)) { bidx = ubase + 2 * q + 1; found = true; }
            }
        }

        s0 = s1;
    }

    float best = valid ? __half2float(best_h) : -FLT_MAX;
#pragma unroll
    for (int off = 8; off > 0; off >>= 1) {
        float ov = __shfl_xor_sync(0xffffffffu, best, off);
        int   oi = __shfl_xor_sync(0xffffffffu, bidx, off);
        if (ov > best || (ov == best && oi < bidx)) { best = ov; bidx = oi; }
    }
    if (valid && sub == 0) {
        uint32_t fb  = __float_as_uint(best);
        uint32_t key = ((int)fb < 0) ? ~fb : (fb | 0x80000000u);
        unsigned long long pk =
            ((unsigned long long)key << 32) | (uint32_t)(0xFFFFFFFFu - (uint32_t)bidx);
        atomicMax(&g_pack[(n * HP + i) * HP + j], pk);
    }
}

// ---------------------------------------------------------------------------
// Kernel 3: gather matched color patch, L1, clip, global sum.
// ---------------------------------------------------------------------------
__global__ __launch_bounds__(1024) void l1_kernel(const float* __restrict__ outf,
                                                  const float* __restrict__ colf,
                                                  float* __restrict__ dout) {
    const int i = blockIdx.x;
    const int n = blockIdx.y;

    __shared__ float l1s[HP];
    __shared__ int   uu[HP];
    if (threadIdx.x < HP) {
        l1s[threadIdx.x] = 0.0f;
        unsigned long long pk = g_pack[(n * HP + i) * HP + threadIdx.x];
        uu[threadIdx.x] = (int)(0xFFFFFFFFu - (uint32_t)(pk & 0xFFFFFFFFull));
    }
    __syncthreads();

    for (int t = threadIdx.x; t < CC * HP; t += 1024) {
        int c = t / HP;
        int j = t - c * HP;
        int u  = uu[j];
        int us = u / USZ;
        int vs = u - us * USZ;

        const float* op = outf + ((size_t)(n * CC + c) * HH + i)  * WW + j;
        const float* cp = colf + ((size_t)(n * CC + c) * HS + us) * WS + vs;

        float s = 0.0f;
#pragma unroll
        for (int a = 0; a < 3; a++)
#pragma unroll
            for (int b = 0; b < 3; b++)
                s += fabsf(op[a * WW + b] - cp[a * WS + b]);
        atomicAdd(&l1s[j], s);
    }
    __syncthreads();

    if (threadIdx.x < HP) {
        float v = fminf(fmaxf(l1s[threadIdx.x], 0.0f), 1000.0f);
        atomicAdd(dout, v);
    }
}

// ---------------------------------------------------------------------------
// Launch
// Inputs (metadata order): 0 output_feat, 1 ref_feat, 2 shape_feat, 3 color_feat
// ---------------------------------------------------------------------------
extern "C" void kernel_launch(void* const* d_in, const int* in_sizes, int n_in,
                              void* d_out, int out_size) {
    const float* output_feat = (const float*)d_in[0];
    const float* ref_feat    = (const float*)d_in[1];
    const float* shape_feat  = (const float*)d_in[2];
    const float* color_feat  = (const float*)d_in[3];
    float* out = (float*)d_out;

    pack_kernel<<<256, 256>>>(ref_feat,   g_Apk, M_R, NB * (CC / 2) * M_R,
                              out, out_size);
    pack_kernel<<<512, 256>>>(shape_feat, g_Bpk, N_S, NB * (CC / 2) * N_S,
                              out, 0);

    dim3 g1(N_S / BN, M_R / BM, NB);    // 128 x 32 x 2
    gemm_kernel<<<g1, 256>>>();

    dim3 g2(16, 16, NB * 2);
    argmax_kernel<<<g2, 256>>>();

    dim3 g3(HP, NB);
    l1_kernel<<<g3, 1024>>>(output_feat, color_feat, out);
}